// round 16
// baseline (speedup 1.0000x reference)
#include <cuda_runtime.h>
#include <cuda_fp16.h>
#include <cstdint>

#define NEGC (-10000000.0f)

// ---------------- device globals ----------------
__device__ __half g_W1T[512 * 256];    // W1T[n][k] = W1[k][n]
__device__ __half g_W1R[256 * 512];    // W1 row-major f16
__device__ __half g_W2T[128 * 1024];   // W2T[j][i] = W2[i][j]
__device__ __half g_X [4096 * 512];    // X = obs @ W1 + b1
__device__ __half g_V [4096 * 256];    // V = X @ W1^T  (v_b = W1 x_b)
__device__ __half g_Ab[4096 * 256];    // abar = beta^T A

// ---------------- helpers ----------------
__device__ __forceinline__ uint32_t smem_u32(const void* p) {
    uint32_t a;
    asm("{ .reg .u64 t; cvta.to.shared.u64 t, %1; cvt.u32.u64 %0, t; }" : "=r"(a) : "l"(p));
    return a;
}
__device__ __forceinline__ void ldsm4(uint32_t* r, uint32_t addr) {
    asm volatile("ldmatrix.sync.aligned.m8n8.x4.shared.b16 {%0,%1,%2,%3}, [%4];"
        : "=r"(r[0]), "=r"(r[1]), "=r"(r[2]), "=r"(r[3]) : "r"(addr));
}
__device__ __forceinline__ void mmah(uint32_t* d, const uint32_t* a, const uint32_t* b) {
    asm volatile("mma.sync.aligned.m16n8k16.row.col.f16.f16.f16.f16 "
        "{%0,%1}, {%2,%3,%4,%5}, {%6,%7}, {%0,%1};"
        : "+r"(d[0]), "+r"(d[1])
        : "r"(a[0]), "r"(a[1]), "r"(a[2]), "r"(a[3]), "r"(b[0]), "r"(b[1]));
}
__device__ __forceinline__ uint32_t sw_up(int u, int row) {
    return (uint32_t)((u & ~7) | ((u ^ row) & 7));
}
// load f16 tile (rows x U 16B-units per row) into swizzled smem
__device__ __forceinline__ void ld_tile(char* dst, const __half* src, int rows, int U,
                                        int srcStride, int t, int T) {
    int total = rows * U;
    for (int idx = t; idx < total; idx += T) {
        int row = idx / U, u = idx - row * U;
        uint4 v = *(const uint4*)(src + (size_t)row * srcStride + u * 8);
        *(uint4*)(dst + (size_t)row * U * 16 + sw_up(u, row) * 16) = v;
    }
}
__device__ __forceinline__ uint32_t h2u(__half2 h) { return *(uint32_t*)&h; }

// ---------------- prep1: weights -> f16 ----------------
__global__ void prep1(const float* __restrict__ W1, const float* __restrict__ W2) {
    int i = blockIdx.x * blockDim.x + threadIdx.x;
    int stride = gridDim.x * blockDim.x;
    for (int idx = i; idx < 512 * 256; idx += stride) {
        int n = idx >> 8, k = idx & 255;
        g_W1T[idx] = __float2half(W1[k * 512 + n]);
    }
    for (int idx = i; idx < 256 * 512; idx += stride)
        g_W1R[idx] = __float2half(W1[idx]);
    for (int idx = i; idx < 128 * 1024; idx += stride) {
        int j = idx >> 10, k = idx & 1023;
        g_W2T[idx] = __float2half(W2[k * 128 + j]);
    }
}

// ---------------- gemm12: X = obs@W1+b1 (to smem+gmem), then V = X@W1^T ----------------
// grid 128 (32 batch rows each), 512 thr.
// smem: OBS 16K @0, X 32K @16K, B 64K @48K, b1s 1K @112K. occ 2.
#define G12_OBS 0u
#define G12_X   16384u
#define G12_B   49152u
#define G12_B1  114688u
#define G12_SMEM 115712u
__global__ __launch_bounds__(512, 2)
void gemm12(const float* __restrict__ obs, const float* __restrict__ b1g) {
    extern __shared__ char sm[];
    const uint32_t sb = smem_u32(sm);
    __half* b1s = (__half*)(sm + G12_B1);
    const int t = threadIdx.x, w = t >> 5, lane = t & 31;
    const int bm = blockIdx.x;

    // obs tile 32x256 fp32 -> f16 swizzled (32 units/row)
    #pragma unroll
    for (int it = 0; it < 2; it++) {
        int idx = it * 512 + t;
        int row = idx >> 5, u = idx & 31;
        const float* src = obs + (size_t)(bm * 32 + row) * 256 + u * 8;
        float4 v0 = *(const float4*)src, v1 = *(const float4*)(src + 4);
        uint4 pk = make_uint4(h2u(__floats2half2_rn(v0.x, v0.y)), h2u(__floats2half2_rn(v0.z, v0.w)),
                              h2u(__floats2half2_rn(v1.x, v1.y)), h2u(__floats2half2_rn(v1.z, v1.w)));
        *(uint4*)(sm + G12_OBS + row * 512 + sw_up(u, row) * 16) = pk;
    }
    if (t < 512) b1s[t] = __float2half(b1g[t]);

    const int wm = w & 1, wn = w >> 1;       // 2 m-slabs x 8 n-slabs (16 cols)
    const int lrow = lane & 15, lkh = lane >> 4;
    const int mrow = wm * 16 + lrow;
    const int nb = wn * 16 + lrow;
    const int g = lane >> 2, c = lane & 3;

    // ---- phase 1: X = obs @ W1 + b1, 4 n-chunks of 128 ----
    for (int npass = 0; npass < 4; npass++) {
        __syncthreads();
        ld_tile(sm + G12_B, g_W1T + (size_t)(npass * 128) * 256, 128, 32, 256, t, 512);
        __syncthreads();
        uint32_t acc[2][2] = {};
        #pragma unroll
        for (int ks = 0; ks < 16; ks++) {
            const int u = ks * 2 + lkh;
            uint32_t af[4], bf[4];
            ldsm4(af, sb + G12_OBS + (uint32_t)(mrow * 512) + sw_up(u, mrow) * 16);
            ldsm4(bf, sb + G12_B + (uint32_t)(nb * 512) + sw_up(u, nb) * 16);
            mmah(acc[0], af, bf); mmah(acc[1], af, bf + 2);
        }
        #pragma unroll
        for (int ni = 0; ni < 2; ni++) {
            const int ncolG = npass * 128 + wn * 16 + ni * 8 + 2 * c;
            const __half2 bias = *(__half2*)&b1s[ncolG];
            const int ux = ncolG >> 3, ob = (ncolG & 7) * 2;
            #pragma unroll
            for (int rr = 0; rr < 2; rr++) {
                const int r = wm * 16 + g + rr * 8;
                const __half2 hv = __hadd2(*(__half2*)&acc[ni][rr], bias);
                *(__half2*)(sm + G12_X + r * 1024 + sw_up(ux, r) * 16 + ob) = hv;
                *(__half2*)(g_X + (size_t)(bm * 32 + r) * 512 + ncolG) = hv;
            }
        }
    }

    // ---- phase 2: V = X @ W1R^T, 2 n-chunks of 128, K=512 in 2 chunks ----
    for (int nc = 0; nc < 2; nc++) {
        uint32_t acc[2][2] = {};
        for (int kc = 0; kc < 2; kc++) {
            __syncthreads();
            ld_tile(sm + G12_B, g_W1R + (size_t)(nc * 128) * 512 + kc * 256, 128, 32, 512, t, 512);
            __syncthreads();
            #pragma unroll
            for (int ks = 0; ks < 16; ks++) {
                const int ux = kc * 32 + ks * 2 + lkh;
                const int ub = ks * 2 + lkh;
                uint32_t af[4], bf[4];
                ldsm4(af, sb + G12_X + (uint32_t)(mrow * 1024) + sw_up(ux, mrow) * 16);
                ldsm4(bf, sb + G12_B + (uint32_t)(nb * 512) + sw_up(ub, nb) * 16);
                mmah(acc[0], af, bf); mmah(acc[1], af, bf + 2);
            }
        }
        #pragma unroll
        for (int ni = 0; ni < 2; ni++) {
            const int ncol = nc * 128 + wn * 16 + ni * 8 + 2 * c;
            #pragma unroll
            for (int rr = 0; rr < 2; rr++) {
                const int r = wm * 16 + g + rr * 8;
                *(__half2*)(g_V + (size_t)(bm * 32 + r) * 256 + ncol) = *(__half2*)&acc[ni][rr];
            }
        }
    }
}

// ---------------- attn (f16, fused dot): stream others; softmax; abar ----------------
__global__ __launch_bounds__(256, 4)
void attn_kernel(const float* __restrict__ others) {
    extern __shared__ char sm[];
    __half* A  = (__half*)sm;              // [64][264] f16 (pad 8)
    float* alp = (float*)(sm + 34304);     // [64]
    const int t = threadIdx.x, w = t >> 5, lane = t & 31;
    const int b = blockIdx.x;

    uint4 vv = *(const uint4*)(g_V + (size_t)b * 256 + lane * 8);
    const __half2* vh = (const __half2*)&vv;
    float2 vf[4];
    #pragma unroll
    for (int i = 0; i < 4; i++) vf[i] = __half22float2(vh[i]);

    const float* src = others + (size_t)b * 16384;
    #pragma unroll
    for (int r = 0; r < 8; r++) {
        const int row = w * 8 + r;
        const float* p = src + row * 256 + lane * 8;
        float4 x0 = *(const float4*)p;
        float4 x1 = *(const float4*)(p + 4);
        float s = x0.x * vf[0].x + x0.y * vf[0].y + x0.z * vf[1].x + x0.w * vf[1].y
                + x1.x * vf[2].x + x1.y * vf[2].y + x1.z * vf[3].x + x1.w * vf[3].y;
        uint4 pk;
        ((__half2*)&pk)[0] = __floats2half2_rn(x0.x, x0.y);
        ((__half2*)&pk)[1] = __floats2half2_rn(x0.z, x0.w);
        ((__half2*)&pk)[2] = __floats2half2_rn(x1.x, x1.y);
        ((__half2*)&pk)[3] = __floats2half2_rn(x1.z, x1.w);
        *(uint4*)((char*)A + row * 528 + lane * 16) = pk;
        #pragma unroll
        for (int off = 16; off; off >>= 1) s += __shfl_xor_sync(~0u, s, off);
        if (lane == 0) alp[row] = s * 0.04419417382415922f;
    }
    __syncthreads();
    if (w == 0) {  // softmax over 64
        float a0 = alp[lane], a1 = alp[lane + 32];
        float m = fmaxf(a0, a1);
        #pragma unroll
        for (int off = 16; off; off >>= 1) m = fmaxf(m, __shfl_xor_sync(~0u, m, off));
        float e0 = __expf(a0 - m), e1 = __expf(a1 - m);
        float s = e0 + e1;
        #pragma unroll
        for (int off = 16; off; off >>= 1) s += __shfl_xor_sync(~0u, s, off);
        float inv = 1.0f / s;
        alp[lane] = e0 * inv; alp[lane + 32] = e1 * inv;
    }
    __syncthreads();
    float acc = 0.f;
    #pragma unroll 16
    for (int n = 0; n < 64; n++)
        acc = fmaf(alp[n], __half2float(A[n * 264 + t]), acc);
    g_Ab[(size_t)b * 256 + t] = __float2half(acc);
}

// ---------------- gemm3: C = Abar@W1 + b1; logits=[X,C]@W2 + b2; softmax+mask ----------------
// grid 128: 32 batch rows each.
__global__ __launch_bounds__(512, 1)
void gemm3(const float* __restrict__ b1g, const float* __restrict__ b2g,
           const int* __restrict__ action_mask, float* __restrict__ out) {
    extern __shared__ char sm[];
    const uint32_t sb = smem_u32(sm);
    char* Xt = sm;              // 32 x 64u (32K)
    char* Ct = sm + 32768;      // 32 x 64u (32K)
    char* At = sm + 65536;      // 32 x 32u (16K)
    char* Bb = sm + 81920;      // 128 x 32u (64K)
    __half* b1s = (__half*)(sm + 147456);
    __half* b2s = (__half*)(sm + 148480);
    float*  ls  = (float*)(sm + 148736);   // [32][132]
    const int t = threadIdx.x, w = t >> 5, lane = t & 31;
    const int bm = blockIdx.x;

    ld_tile(Xt, g_X  + (size_t)(bm * 32) * 512, 32, 64, 512, t, 512);
    ld_tile(At, g_Ab + (size_t)(bm * 32) * 256, 32, 32, 256, t, 512);
    b1s[t & 511] = __float2half(b1g[t & 511]);
    if (t < 128) b2s[t] = __float2half(b2g[t]);

    const int wm = w & 1, wn = w >> 1;
    const int lrow = lane & 15, lkh = lane >> 4;
    const int mrow = wm * 16 + lrow;
    const int nb = wn * 16 + lrow;
    const int g = lane >> 2, c = lane & 3;

    // ---- phase 1: C = Abar @ W1 + b1, stored f16 swizzled into Ct ----
    for (int npass = 0; npass < 4; npass++) {
        __syncthreads();
        ld_tile(Bb, g_W1T + (size_t)(npass * 128) * 256, 128, 32, 256, t, 512);
        __syncthreads();
        uint32_t acc[2][2] = {};
        #pragma unroll
        for (int ks = 0; ks < 16; ks++) {
            const int u = ks * 2 + lkh;
            uint32_t af[4], bf[4];
            ldsm4(af, sb + 65536u + (uint32_t)(mrow * 512) + sw_up(u, mrow) * 16);
            ldsm4(bf, sb + 81920u + (uint32_t)(nb * 512) + sw_up(u, nb) * 16);
            mmah(acc[0], af, bf); mmah(acc[1], af, bf + 2);
        }
        #pragma unroll
        for (int ni = 0; ni < 2; ni++) {
            const int ncolG = npass * 128 + wn * 16 + ni * 8 + 2 * c;
            const __half2 bias = *(__half2*)&b1s[ncolG];
            const int u = ncolG >> 3, ob = (ncolG & 7) * 2;
            const int r0 = wm * 16 + g;
            *(__half2*)(Ct + r0 * 1024 + sw_up(u, r0) * 16 + ob) =
                __hadd2(*(__half2*)&acc[ni][0], bias);
            *(__half2*)(Ct + (r0 + 8) * 1024 + sw_up(u, r0 + 8) * 16 + ob) =
                __hadd2(*(__half2*)&acc[ni][1], bias);
        }
    }

    // ---- phase 2: logits[32][128] = [X,C] @ W2 (K=1024 in 4 chunks) ----
    uint32_t acc[2][2] = {};
    for (int kc = 0; kc < 4; kc++) {
        __syncthreads();
        ld_tile(Bb, g_W2T + kc * 256, 128, 32, 1024, t, 512);
        __syncthreads();
        const uint32_t abase = sb + ((kc < 2) ? 0u : 32768u);
        const int uoff = (kc & 1) * 32;
        #pragma unroll
        for (int ks = 0; ks < 16; ks++) {
            const int u = uoff + ks * 2 + lkh;
            const int u2 = ks * 2 + lkh;
            uint32_t af[4], bf[4];
            ldsm4(af, abase + (uint32_t)(mrow * 1024) + sw_up(u, mrow) * 16);
            ldsm4(bf, sb + 81920u + (uint32_t)(nb * 512) + sw_up(u2, nb) * 16);
            mmah(acc[0], af, bf); mmah(acc[1], af, bf + 2);
        }
    }
    #pragma unroll
    for (int ni = 0; ni < 2; ni++) {
        const int col = wn * 16 + ni * 8 + 2 * c;
        float2 b2v = __half22float2(*(__half2*)&b2s[col]);
        const int r0 = wm * 16 + g;
        float2 v0 = __half22float2(*(__half2*)&acc[ni][0]);
        float2 v1 = __half22float2(*(__half2*)&acc[ni][1]);
        ls[r0 * 132 + col]           = v0.x + b2v.x;
        ls[r0 * 132 + col + 1]       = v0.y + b2v.y;
        ls[(r0 + 8) * 132 + col]     = v1.x + b2v.x;
        ls[(r0 + 8) * 132 + col + 1] = v1.y + b2v.y;
    }
    __syncthreads();

    // ---- softmax(128) + mask + write: warp w handles rows 2w, 2w+1 ----
    #pragma unroll
    for (int rr = 0; rr < 2; rr++) {
        const int row = w * 2 + rr;
        float v0 = ls[row * 132 + lane],      v1 = ls[row * 132 + lane + 32];
        float v2 = ls[row * 132 + lane + 64], v3 = ls[row * 132 + lane + 96];
        float m = fmaxf(fmaxf(v0, v1), fmaxf(v2, v3));
        #pragma unroll
        for (int off = 16; off; off >>= 1) m = fmaxf(m, __shfl_xor_sync(~0u, m, off));
        float e0 = __expf(v0 - m), e1 = __expf(v1 - m);
        float e2 = __expf(v2 - m), e3 = __expf(v3 - m);
        float s = e0 + e1 + e2 + e3;
        #pragma unroll
        for (int off = 16; off; off >>= 1) s += __shfl_xor_sync(~0u, s, off);
        const float inv = 1.0f / s;
        const size_t gb = (size_t)(bm * 32 + row);
        const int* mk = action_mask + gb * 128;
        float* op = out + gb * 128;
        op[lane]      = e0 * inv + NEGC * (1.0f - (float)mk[lane]);
        op[lane + 32] = e1 * inv + NEGC * (1.0f - (float)mk[lane + 32]);
        op[lane + 64] = e2 * inv + NEGC * (1.0f - (float)mk[lane + 64]);
        op[lane + 96] = e3 * inv + NEGC * (1.0f - (float)mk[lane + 96]);
    }
}

extern "C" void kernel_launch(void* const* d_in, const int* in_sizes, int n_in,
                              void* d_out, int out_size)
{
    const float* obs_x       = (const float*)d_in[0];
    const float* others      = (const float*)d_in[1];
    const int*   action_mask = (const int*)  d_in[2];
    const float* W1          = (const float*)d_in[3];
    const float* b1          = (const float*)d_in[4];
    const float* W2          = (const float*)d_in[5];
    const float* b2          = (const float*)d_in[6];
    // d_in[7..10] = W3,b3,W4,b4: dead in reference forward(), unused.

    cudaFuncSetAttribute(gemm12,      cudaFuncAttributeMaxDynamicSharedMemorySize, G12_SMEM);
    cudaFuncSetAttribute(attn_kernel, cudaFuncAttributeMaxDynamicSharedMemorySize, 34816);
    cudaFuncSetAttribute(gemm3,       cudaFuncAttributeMaxDynamicSharedMemorySize, 165632);

    prep1<<<256, 256>>>(W1, W2);
    gemm12<<<128, 512, G12_SMEM>>>(obs_x, b1);
    attn_kernel<<<4096, 256, 34816>>>(others);
    gemm3<<<128, 512, 165632>>>(b1, b2, action_mask, (float*)d_out);
}

// round 17
// speedup vs baseline: 1.0826x; 1.0826x over previous
#include <cuda_runtime.h>
#include <cuda_fp16.h>
#include <cstdint>

#define NEGC (-10000000.0f)

// ---------------- device globals ----------------
__device__ __half g_W1T[512 * 256];    // W1T[n][k] = W1[k][n]
__device__ __half g_W1R[256 * 512];    // W1 row-major f16
__device__ __half g_W2T[128 * 1024];   // W2T[j][i] = W2[i][j]
__device__ __half g_X [4096 * 512];    // X = obs @ W1 + b1
__device__ __half g_V [4096 * 256];    // V = X @ W1^T  (v_b = W1 x_b)
__device__ __half g_Ab[4096 * 256];    // abar = beta^T A

// ---------------- helpers ----------------
__device__ __forceinline__ uint32_t smem_u32(const void* p) {
    uint32_t a;
    asm("{ .reg .u64 t; cvta.to.shared.u64 t, %1; cvt.u32.u64 %0, t; }" : "=r"(a) : "l"(p));
    return a;
}
__device__ __forceinline__ void ldsm4(uint32_t* r, uint32_t addr) {
    asm volatile("ldmatrix.sync.aligned.m8n8.x4.shared.b16 {%0,%1,%2,%3}, [%4];"
        : "=r"(r[0]), "=r"(r[1]), "=r"(r[2]), "=r"(r[3]) : "r"(addr));
}
__device__ __forceinline__ void mmah(uint32_t* d, const uint32_t* a, const uint32_t* b) {
    asm volatile("mma.sync.aligned.m16n8k16.row.col.f16.f16.f16.f16 "
        "{%0,%1}, {%2,%3,%4,%5}, {%6,%7}, {%0,%1};"
        : "+r"(d[0]), "+r"(d[1])
        : "r"(a[0]), "r"(a[1]), "r"(a[2]), "r"(a[3]), "r"(b[0]), "r"(b[1]));
}
__device__ __forceinline__ uint32_t sw_up(int u, int row) {
    return (uint32_t)((u & ~7) | ((u ^ row) & 7));
}
// load f16 tile (rows x U 16B-units per row) into swizzled smem
__device__ __forceinline__ void ld_tile(char* dst, const __half* src, int rows, int U,
                                        int srcStride, int t, int T) {
    int total = rows * U;
    for (int idx = t; idx < total; idx += T) {
        int row = idx / U, u = idx - row * U;
        uint4 v = *(const uint4*)(src + (size_t)row * srcStride + u * 8);
        *(uint4*)(dst + (size_t)row * U * 16 + sw_up(u, row) * 16) = v;
    }
}
__device__ __forceinline__ uint32_t h2u(__half2 h) { return *(uint32_t*)&h; }

// ---------------- prep1: weights -> f16 (smem-tiled coalesced transposes) ----------------
// bid 0..31 : W1T tiles (kt=bid&3, nt=bid>>2), 64x64
// bid 32..63: W2T tiles (b=bid-32: it=b&15, jt=b>>4), 64x64
// bid 64..67: W1R copy (coalesced convert)
__global__ __launch_bounds__(256)
void prep1(const float* __restrict__ W1, const float* __restrict__ W2) {
    __shared__ float smf[64][65];
    const int bid = blockIdx.x, t = threadIdx.x;

    if (bid < 32) {
        const int kt = bid & 3, nt = bid >> 2;
        #pragma unroll
        for (int i = 0; i < 16; i++) {
            int idx = i * 256 + t, r = idx >> 6, c = idx & 63;
            smf[r][c] = W1[(size_t)(kt * 64 + r) * 512 + nt * 64 + c];
        }
        __syncthreads();
        #pragma unroll
        for (int i = 0; i < 16; i++) {
            int idx = i * 256 + t, r = idx >> 6, c = idx & 63;
            g_W1T[(size_t)(nt * 64 + r) * 256 + kt * 64 + c] = __float2half(smf[c][r]);
        }
    } else if (bid < 64) {
        const int b = bid - 32, it = b & 15, jt = b >> 4;
        #pragma unroll
        for (int i = 0; i < 16; i++) {
            int idx = i * 256 + t, r = idx >> 6, c = idx & 63;
            smf[r][c] = W2[(size_t)(it * 64 + r) * 128 + jt * 64 + c];
        }
        __syncthreads();
        #pragma unroll
        for (int i = 0; i < 16; i++) {
            int idx = i * 256 + t, r = idx >> 6, c = idx & 63;
            g_W2T[(size_t)(jt * 64 + r) * 1024 + it * 64 + c] = __float2half(smf[c][r]);
        }
    } else {
        const int b = bid - 64;   // 4 CTAs cover 256*512 = 131072 elems, 32768 per CTA
        const float* src = W1 + (size_t)b * 32768;
        __half* dst = g_W1R + (size_t)b * 32768;
        #pragma unroll
        for (int i = 0; i < 32; i++) {
            int e = (i * 256 + t) * 4;
            float4 v = *(const float4*)(src + e);
            *(uint2*)(dst + e) = make_uint2(h2u(__floats2half2_rn(v.x, v.y)),
                                            h2u(__floats2half2_rn(v.z, v.w)));
        }
    }
}

// ---------------- gemm12: X = obs@W1+b1 (to smem+gmem), then V = X@W1^T ----------------
// grid 128 (32 batch rows each), 512 thr. occ 2.
#define G12_OBS 0u
#define G12_X   16384u
#define G12_B   49152u
#define G12_B1  114688u
#define G12_SMEM 115712u
__global__ __launch_bounds__(512, 2)
void gemm12(const float* __restrict__ obs, const float* __restrict__ b1g) {
    extern __shared__ char sm[];
    const uint32_t sb = smem_u32(sm);
    __half* b1s = (__half*)(sm + G12_B1);
    const int t = threadIdx.x, w = t >> 5, lane = t & 31;
    const int bm = blockIdx.x;

    #pragma unroll
    for (int it = 0; it < 2; it++) {
        int idx = it * 512 + t;
        int row = idx >> 5, u = idx & 31;
        const float* src = obs + (size_t)(bm * 32 + row) * 256 + u * 8;
        float4 v0 = *(const float4*)src, v1 = *(const float4*)(src + 4);
        uint4 pk = make_uint4(h2u(__floats2half2_rn(v0.x, v0.y)), h2u(__floats2half2_rn(v0.z, v0.w)),
                              h2u(__floats2half2_rn(v1.x, v1.y)), h2u(__floats2half2_rn(v1.z, v1.w)));
        *(uint4*)(sm + G12_OBS + row * 512 + sw_up(u, row) * 16) = pk;
    }
    if (t < 512) b1s[t] = __float2half(b1g[t]);

    const int wm = w & 1, wn = w >> 1;
    const int lrow = lane & 15, lkh = lane >> 4;
    const int mrow = wm * 16 + lrow;
    const int nb = wn * 16 + lrow;
    const int g = lane >> 2, c = lane & 3;

    for (int npass = 0; npass < 4; npass++) {
        __syncthreads();
        ld_tile(sm + G12_B, g_W1T + (size_t)(npass * 128) * 256, 128, 32, 256, t, 512);
        __syncthreads();
        uint32_t acc[2][2] = {};
        #pragma unroll
        for (int ks = 0; ks < 16; ks++) {
            const int u = ks * 2 + lkh;
            uint32_t af[4], bf[4];
            ldsm4(af, sb + G12_OBS + (uint32_t)(mrow * 512) + sw_up(u, mrow) * 16);
            ldsm4(bf, sb + G12_B + (uint32_t)(nb * 512) + sw_up(u, nb) * 16);
            mmah(acc[0], af, bf); mmah(acc[1], af, bf + 2);
        }
        #pragma unroll
        for (int ni = 0; ni < 2; ni++) {
            const int ncolG = npass * 128 + wn * 16 + ni * 8 + 2 * c;
            const __half2 bias = *(__half2*)&b1s[ncolG];
            const int ux = ncolG >> 3, ob = (ncolG & 7) * 2;
            #pragma unroll
            for (int rr = 0; rr < 2; rr++) {
                const int r = wm * 16 + g + rr * 8;
                const __half2 hv = __hadd2(*(__half2*)&acc[ni][rr], bias);
                *(__half2*)(sm + G12_X + r * 1024 + sw_up(ux, r) * 16 + ob) = hv;
                *(__half2*)(g_X + (size_t)(bm * 32 + r) * 512 + ncolG) = hv;
            }
        }
    }

    for (int nc = 0; nc < 2; nc++) {
        uint32_t acc[2][2] = {};
        for (int kc = 0; kc < 2; kc++) {
            __syncthreads();
            ld_tile(sm + G12_B, g_W1R + (size_t)(nc * 128) * 512 + kc * 256, 128, 32, 512, t, 512);
            __syncthreads();
            #pragma unroll
            for (int ks = 0; ks < 16; ks++) {
                const int ux = kc * 32 + ks * 2 + lkh;
                const int ub = ks * 2 + lkh;
                uint32_t af[4], bf[4];
                ldsm4(af, sb + G12_X + (uint32_t)(mrow * 1024) + sw_up(ux, mrow) * 16);
                ldsm4(bf, sb + G12_B + (uint32_t)(nb * 512) + sw_up(ub, nb) * 16);
                mmah(acc[0], af, bf); mmah(acc[1], af, bf + 2);
            }
        }
        #pragma unroll
        for (int ni = 0; ni < 2; ni++) {
            const int ncol = nc * 128 + wn * 16 + ni * 8 + 2 * c;
            #pragma unroll
            for (int rr = 0; rr < 2; rr++) {
                const int r = wm * 16 + g + rr * 8;
                *(__half2*)(g_V + (size_t)(bm * 32 + r) * 256 + ncol) = *(__half2*)&acc[ni][rr];
            }
        }
    }
}

// ---------------- attn (f16, fused dot): stream others; softmax; abar ----------------
__global__ __launch_bounds__(256, 4)
void attn_kernel(const float* __restrict__ others) {
    extern __shared__ char sm[];
    __half* A  = (__half*)sm;              // [64][264] f16 (pad 8)
    float* alp = (float*)(sm + 34304);     // [64]
    const int t = threadIdx.x, w = t >> 5, lane = t & 31;
    const int b = blockIdx.x;

    uint4 vv = *(const uint4*)(g_V + (size_t)b * 256 + lane * 8);
    const __half2* vh = (const __half2*)&vv;
    float2 vf[4];
    #pragma unroll
    for (int i = 0; i < 4; i++) vf[i] = __half22float2(vh[i]);

    const float* src = others + (size_t)b * 16384;
    #pragma unroll
    for (int r = 0; r < 8; r++) {
        const int row = w * 8 + r;
        const float* p = src + row * 256 + lane * 8;
        float4 x0 = *(const float4*)p;
        float4 x1 = *(const float4*)(p + 4);
        float s = x0.x * vf[0].x + x0.y * vf[0].y + x0.z * vf[1].x + x0.w * vf[1].y
                + x1.x * vf[2].x + x1.y * vf[2].y + x1.z * vf[3].x + x1.w * vf[3].y;
        uint4 pk;
        ((__half2*)&pk)[0] = __floats2half2_rn(x0.x, x0.y);
        ((__half2*)&pk)[1] = __floats2half2_rn(x0.z, x0.w);
        ((__half2*)&pk)[2] = __floats2half2_rn(x1.x, x1.y);
        ((__half2*)&pk)[3] = __floats2half2_rn(x1.z, x1.w);
        *(uint4*)((char*)A + row * 528 + lane * 16) = pk;
        #pragma unroll
        for (int off = 16; off; off >>= 1) s += __shfl_xor_sync(~0u, s, off);
        if (lane == 0) alp[row] = s * 0.04419417382415922f;
    }
    __syncthreads();
    if (w == 0) {
        float a0 = alp[lane], a1 = alp[lane + 32];
        float m = fmaxf(a0, a1);
        #pragma unroll
        for (int off = 16; off; off >>= 1) m = fmaxf(m, __shfl_xor_sync(~0u, m, off));
        float e0 = __expf(a0 - m), e1 = __expf(a1 - m);
        float s = e0 + e1;
        #pragma unroll
        for (int off = 16; off; off >>= 1) s += __shfl_xor_sync(~0u, s, off);
        float inv = 1.0f / s;
        alp[lane] = e0 * inv; alp[lane + 32] = e1 * inv;
    }
    __syncthreads();
    float acc = 0.f;
    #pragma unroll 16
    for (int n = 0; n < 64; n++)
        acc = fmaf(alp[n], __half2float(A[n * 264 + t]), acc);
    g_Ab[(size_t)b * 256 + t] = __float2half(acc);
}

// ---------------- gemm3: C = Abar@W1 + b1; logits=[X,C]@W2 + b2 (cp.async B pipeline) ----------------
// grid 128 (32 rows each), 512 thr, occ 1.
// smem: Xt 32K@0, Ct 32K@32K, At 16K@64K, B0 64K@80K(81920), B1 64K@147456,
//       b1s@212992, b2s@214016, ls overlays Xt.
#define G3_XT 0u
#define G3_CT 32768u
#define G3_AT 65536u
#define G3_B0 81920u
#define G3_B1 147456u
#define G3_B1S 212992u
#define G3_B2S 214016u
#define G3_SMEM 214272u
__device__ __forceinline__ void g3_issue(uint32_t sb, int c, int t) {
    const uint32_t dst = sb + ((c & 1) ? G3_B1 : G3_B0);
    const __half* src = (c < 4) ? (g_W1T + (size_t)c * 128 * 256)
                                : (g_W2T + (size_t)(c - 4) * 256);
    const int stride = (c < 4) ? 256 : 1024;
    #pragma unroll
    for (int i = 0; i < 8; i++) {
        int idx = i * 512 + t;
        int row = idx >> 5, u = idx & 31;
        uint32_t d = dst + (uint32_t)row * 512u + sw_up(u, row) * 16u;
        const void* s = src + (size_t)row * stride + u * 8;
        asm volatile("cp.async.cg.shared.global [%0], [%1], 16;" :: "r"(d), "l"(s));
    }
    asm volatile("cp.async.commit_group;" ::: "memory");
}
__global__ __launch_bounds__(512, 1)
void gemm3(const float* __restrict__ b1g, const float* __restrict__ b2g,
           const int* __restrict__ action_mask, float* __restrict__ out) {
    extern __shared__ char sm[];
    const uint32_t sb = smem_u32(sm);
    char* Ct = sm + G3_CT;
    __half* b1s = (__half*)(sm + G3_B1S);
    __half* b2s = (__half*)(sm + G3_B2S);
    float*  ls  = (float*)sm;              // overlays Xt after mainloop
    const int t = threadIdx.x, w = t >> 5, lane = t & 31;
    const int bm = blockIdx.x;

    g3_issue(sb, 0, t);
    g3_issue(sb, 1, t);

    ld_tile(sm + G3_XT, g_X  + (size_t)(bm * 32) * 512, 32, 64, 512, t, 512);
    ld_tile(sm + G3_AT, g_Ab + (size_t)(bm * 32) * 256, 32, 32, 256, t, 512);
    b1s[t & 511] = __float2half(b1g[t & 511]);
    if (t < 128) b2s[t] = __float2half(b2g[t]);

    const int wm = w & 1, wn = w >> 1;
    const int lrow = lane & 15, lkh = lane >> 4;
    const int mrow = wm * 16 + lrow;
    const int nb = wn * 16 + lrow;
    const int g = lane >> 2, c = lane & 3;

    uint32_t acc2[2][2] = {};   // phase-2 persistent accumulators

    for (int ch = 0; ch < 8; ch++) {
        if (ch < 7) asm volatile("cp.async.wait_group 1;" ::: "memory");
        else        asm volatile("cp.async.wait_group 0;" ::: "memory");
        __syncthreads();
        const uint32_t bbuf = sb + ((ch & 1) ? G3_B1 : G3_B0);

        if (ch < 4) {
            // phase 1: C chunk npass=ch
            uint32_t acc[2][2] = {};
            #pragma unroll
            for (int ks = 0; ks < 16; ks++) {
                const int u = ks * 2 + lkh;
                uint32_t af[4], bf[4];
                ldsm4(af, sb + G3_AT + (uint32_t)(mrow * 512) + sw_up(u, mrow) * 16);
                ldsm4(bf, bbuf + (uint32_t)(nb * 512) + sw_up(u, nb) * 16);
                mmah(acc[0], af, bf); mmah(acc[1], af, bf + 2);
            }
            #pragma unroll
            for (int ni = 0; ni < 2; ni++) {
                const int ncolG = ch * 128 + wn * 16 + ni * 8 + 2 * c;
                const __half2 bias = *(__half2*)&b1s[ncolG];
                const int u = ncolG >> 3, ob = (ncolG & 7) * 2;
                const int r0 = wm * 16 + g;
                *(__half2*)(Ct + r0 * 1024 + sw_up(u, r0) * 16 + ob) =
                    __hadd2(*(__half2*)&acc[ni][0], bias);
                *(__half2*)(Ct + (r0 + 8) * 1024 + sw_up(u, r0 + 8) * 16 + ob) =
                    __hadd2(*(__half2*)&acc[ni][1], bias);
            }
        } else {
            // phase 2: logits accumulate, kc = ch-4
            const int kc = ch - 4;
            const uint32_t abase = sb + ((kc < 2) ? G3_XT : G3_CT);
            const int uoff = (kc & 1) * 32;
            #pragma unroll
            for (int ks = 0; ks < 16; ks++) {
                const int u = uoff + ks * 2 + lkh;
                const int u2 = ks * 2 + lkh;
                uint32_t af[4], bf[4];
                ldsm4(af, abase + (uint32_t)(mrow * 1024) + sw_up(u, mrow) * 16);
                ldsm4(bf, bbuf + (uint32_t)(nb * 512) + sw_up(u2, nb) * 16);
                mmah(acc2[0], af, bf); mmah(acc2[1], af, bf + 2);
            }
        }
        __syncthreads();            // all warps done reading buf ch
        if (ch + 2 < 8) g3_issue(sb, ch + 2, t);
    }

    // ---- epilogue: +b2 -> ls (overlays Xt) ----
    #pragma unroll
    for (int ni = 0; ni < 2; ni++) {
        const int col = wn * 16 + ni * 8 + 2 * c;
        float2 b2v = __half22float2(*(__half2*)&b2s[col]);
        const int r0 = wm * 16 + g;
        float2 v0 = __half22float2(*(__half2*)&acc2[ni][0]);
        float2 v1 = __half22float2(*(__half2*)&acc2[ni][1]);
        ls[r0 * 132 + col]           = v0.x + b2v.x;
        ls[r0 * 132 + col + 1]       = v0.y + b2v.y;
        ls[(r0 + 8) * 132 + col]     = v1.x + b2v.x;
        ls[(r0 + 8) * 132 + col + 1] = v1.y + b2v.y;
    }
    __syncthreads();

    // ---- softmax(128) + mask + write: warp w -> rows 2w, 2w+1 ----
    #pragma unroll
    for (int rr = 0; rr < 2; rr++) {
        const int row = w * 2 + rr;
        float v0 = ls[row * 132 + lane],      v1 = ls[row * 132 + lane + 32];
        float v2 = ls[row * 132 + lane + 64], v3 = ls[row * 132 + lane + 96];
        float m = fmaxf(fmaxf(v0, v1), fmaxf(v2, v3));
        #pragma unroll
        for (int off = 16; off; off >>= 1) m = fmaxf(m, __shfl_xor_sync(~0u, m, off));
        float e0 = __expf(v0 - m), e1 = __expf(v1 - m);
        float e2 = __expf(v2 - m), e3 = __expf(v3 - m);
        float s = e0 + e1 + e2 + e3;
        #pragma unroll
        for (int off = 16; off; off >>= 1) s += __shfl_xor_sync(~0u, s, off);
        const float inv = 1.0f / s;
        const size_t gb = (size_t)(bm * 32 + row);
        const int* mk = action_mask + gb * 128;
        float* op = out + gb * 128;
        op[lane]      = e0 * inv + NEGC * (1.0f - (float)mk[lane]);
        op[lane + 32] = e1 * inv + NEGC * (1.0f - (float)mk[lane + 32]);
        op[lane + 64] = e2 * inv + NEGC * (1.0f - (float)mk[lane + 64]);
        op[lane + 96] = e3 * inv + NEGC * (1.0f - (float)mk[lane + 96]);
    }
}

extern "C" void kernel_launch(void* const* d_in, const int* in_sizes, int n_in,
                              void* d_out, int out_size)
{
    const float* obs_x       = (const float*)d_in[0];
    const float* others      = (const float*)d_in[1];
    const int*   action_mask = (const int*)  d_in[2];
    const float* W1          = (const float*)d_in[3];
    const float* b1          = (const float*)d_in[4];
    const float* W2          = (const float*)d_in[5];
    const float* b2          = (const float*)d_in[6];
    // d_in[7..10] = W3,b3,W4,b4: dead in reference forward(), unused.

    cudaFuncSetAttribute(gemm12,      cudaFuncAttributeMaxDynamicSharedMemorySize, G12_SMEM);
    cudaFuncSetAttribute(attn_kernel, cudaFuncAttributeMaxDynamicSharedMemorySize, 34816);
    cudaFuncSetAttribute(gemm3,       cudaFuncAttributeMaxDynamicSharedMemorySize, G3_SMEM);

    prep1<<<68, 256>>>(W1, W2);
    gemm12<<<128, 512, G12_SMEM>>>(obs_x, b1);
    attn_kernel<<<4096, 256, 34816>>>(others);
    gemm3<<<128, 512, G3_SMEM>>>(b1, b2, action_mask, (float*)d_out);
}